// round 1
// baseline (speedup 1.0000x reference)
#include <cuda_runtime.h>
#include <math_constants.h>
#include <stdint.h>

#define T_TOK 32768
#define DIM   256
#define K_CB  8192
#define BM    64
#define BN    128
#define BD    16

// ---- device scratch (static: no allocations allowed) ----
__device__ float        g_x2[T_TOK];
__device__ float        g_w2[K_CB];
__device__ int          g_best[T_TOK];
__device__ unsigned int g_used[K_CB / 32];   // 256 words
__device__ double       g_part[1024];

// ---------------------------------------------------------------------------
__global__ void zero_used_k() {
    g_used[threadIdx.x] = 0u;
}

// one warp per row; rows [0,T_TOK) = z tokens (x2), [T_TOK, T_TOK+K_CB) = codebook (w2)
__global__ void row_norms_k(const float* __restrict__ z, const float* __restrict__ cb) {
    int lane = threadIdx.x & 31;
    int row  = blockIdx.x * 8 + (threadIdx.x >> 5);
    const float* p = (row < T_TOK) ? (z + (size_t)row * DIM)
                                   : (cb + (size_t)(row - T_TOK) * DIM);
    float s = 0.f;
#pragma unroll
    for (int j = 0; j < 8; ++j) {
        float v = p[lane + 32 * j];
        s = __fmaf_rn(v, v, s);
    }
#pragma unroll
    for (int off = 16; off; off >>= 1)
        s += __shfl_xor_sync(0xffffffffu, s, off);
    if (lane == 0) {
        if (row < T_TOK) g_x2[row] = s;
        else             g_w2[row - T_TOK] = s;
    }
}

// ---------------------------------------------------------------------------
// Fused distance + argmin. Block = 64 tokens; z tile resident in SMEM,
// codebook streamed in 128x16 tiles with register-prefetch double buffering.
// Each thread: 8 tokens x 4 codewords accumulator tile.
__global__ __launch_bounds__(256, 2)
void vq_argmin_k(const float* __restrict__ z, const float* __restrict__ cb) {
    extern __shared__ float smem[];
    float* as = smem;                 // [DIM][BM]  (d-major, token minor) 64KB
    float* bs = smem + DIM * BM;      // [2][BD][BN]                       16KB

    int tid  = threadIdx.x;
    int lane = tid & 31;
    int wid  = tid >> 5;              // warp 0..7 -> tokens wid*8..+8
    int t0   = blockIdx.x * BM;

    // load z tile transposed
    {
        int tt = tid & 63;
        int dc = (tid >> 6) << 6;     // 0,64,128,192
        const float4* zr = (const float4*)(z + (size_t)(t0 + tt) * DIM + dc);
#pragma unroll
        for (int i = 0; i < 16; ++i) {
            float4 v = zr[i];
            int d = dc + i * 4;
            as[(d + 0) * BM + tt] = v.x;
            as[(d + 1) * BM + tt] = v.y;
            as[(d + 2) * BM + tt] = v.z;
            as[(d + 3) * BM + tt] = v.w;
        }
    }

    float x2r[8];
#pragma unroll
    for (int i = 0; i < 8; ++i) x2r[i] = g_x2[t0 + wid * 8 + i];

    float minv[8];
    int   mini[8];
#pragma unroll
    for (int i = 0; i < 8; ++i) { minv[i] = CUDART_INF_F; mini[i] = 0; }

    int kk = tid & 127;               // codeword row loaded by this thread
    int dh = (tid >> 7) * 8;          // d-offset half: 0 or 8

    __syncthreads();

    for (int k0 = 0; k0 < K_CB; k0 += BN) {
        float acc[8][4];
#pragma unroll
        for (int i = 0; i < 8; ++i)
#pragma unroll
            for (int j = 0; j < 4; ++j) acc[i][j] = 0.f;

        const float* cbr = cb + (size_t)(k0 + kk) * DIM + dh;
        float4 r0 = *(const float4*)(cbr + 0);
        float4 r1 = *(const float4*)(cbr + 4);
        int buf = 0;

        for (int ds = 0; ds < DIM; ds += BD) {
            float* bw = bs + buf * (BD * BN);
            bw[(dh + 0) * BN + kk] = r0.x;
            bw[(dh + 1) * BN + kk] = r0.y;
            bw[(dh + 2) * BN + kk] = r0.z;
            bw[(dh + 3) * BN + kk] = r0.w;
            bw[(dh + 4) * BN + kk] = r1.x;
            bw[(dh + 5) * BN + kk] = r1.y;
            bw[(dh + 6) * BN + kk] = r1.z;
            bw[(dh + 7) * BN + kk] = r1.w;
            __syncthreads();

            if (ds + BD < DIM) {
                const float* nx = cbr + ds + BD;
                r0 = *(const float4*)(nx + 0);
                r1 = *(const float4*)(nx + 4);
            }

            const float* br = bs + buf * (BD * BN);
#pragma unroll
            for (int dd = 0; dd < BD; ++dd) {
                const float4* ap = (const float4*)(as + (ds + dd) * BM + wid * 8);
                float4 a0 = ap[0];
                float4 a1 = ap[1];
                float4 bv = *(const float4*)(br + dd * BN + lane * 4);
                float a[8] = {a0.x, a0.y, a0.z, a0.w, a1.x, a1.y, a1.z, a1.w};
                float b[4] = {bv.x, bv.y, bv.z, bv.w};
#pragma unroll
                for (int i = 0; i < 8; ++i)
#pragma unroll
                    for (int j = 0; j < 4; ++j)
                        acc[i][j] = __fmaf_rn(a[i], b[j], acc[i][j]);
            }
            buf ^= 1;
            __syncthreads();
        }

        // epilogue: mimic reference rounding: ((x2 - (2*xw)) + w2), fp32 each step
#pragma unroll
        for (int j = 0; j < 4; ++j) {
            int k = k0 + lane * 4 + j;
            float w2 = g_w2[k];
#pragma unroll
            for (int i = 0; i < 8; ++i) {
                float m    = __fmul_rn(2.0f, acc[i][j]);
                float t1   = __fsub_rn(x2r[i], m);
                float dist = __fadd_rn(t1, w2);
                if (dist < minv[i]) { minv[i] = dist; mini[i] = k; }
            }
        }
    }

    // cross-lane argmin (first-index tie-break, matching jnp.argmin)
#pragma unroll
    for (int i = 0; i < 8; ++i) {
        float v = minv[i];
        int idx = mini[i];
#pragma unroll
        for (int off = 16; off; off >>= 1) {
            float ov = __shfl_xor_sync(0xffffffffu, v, off);
            int   oi = __shfl_xor_sync(0xffffffffu, idx, off);
            if (ov < v || (ov == v && oi < idx)) { v = ov; idx = oi; }
        }
        if (lane == 0) g_best[t0 + wid * 8 + i] = idx;
    }
}

// ---------------------------------------------------------------------------
// Gather z_q, emit z_q_ste with the reference's STE round-trip rounding,
// accumulate sum((z - z_q_ste)^2) deterministically, mark used codewords.
__global__ void gather_out_k(const float* __restrict__ z, const float* __restrict__ cb,
                             float* __restrict__ out) {
    __shared__ double sd[256];
    int tid  = threadIdx.x;
    int lane = tid & 31;
    int wid  = tid >> 5;
    int tbase = blockIdx.x * 32 + wid * 4;
    double s = 0.0;

    for (int r = 0; r < 4; ++r) {
        int t   = tbase + r;
        int idx = g_best[t];
        if (lane == 0) atomicOr(&g_used[idx >> 5], 1u << (idx & 31));
        const float4* qr  = (const float4*)(cb + (size_t)idx * DIM);
        const float4* zr  = (const float4*)(z + (size_t)t * DIM);
        float4*       orow = (float4*)(out + (size_t)t * DIM);
#pragma unroll
        for (int h = 0; h < 2; ++h) {
            float4 q  = qr[lane + 32 * h];
            float4 zv = zr[lane + 32 * h];
            float4 o;
            o.x = __fadd_rn(zv.x, __fsub_rn(q.x, zv.x));
            o.y = __fadd_rn(zv.y, __fsub_rn(q.y, zv.y));
            o.z = __fadd_rn(zv.z, __fsub_rn(q.z, zv.z));
            o.w = __fadd_rn(zv.w, __fsub_rn(q.w, zv.w));
            orow[lane + 32 * h] = o;
            float dx = __fsub_rn(zv.x, o.x);
            float dy = __fsub_rn(zv.y, o.y);
            float dz = __fsub_rn(zv.z, o.z);
            float dw = __fsub_rn(zv.w, o.w);
            s += (double)__fmul_rn(dx, dx);
            s += (double)__fmul_rn(dy, dy);
            s += (double)__fmul_rn(dz, dz);
            s += (double)__fmul_rn(dw, dw);
        }
    }
    sd[tid] = s;
    __syncthreads();
    for (int o = 128; o; o >>= 1) {
        if (tid < o) sd[tid] += sd[tid + o];
        __syncthreads();
    }
    if (tid == 0) g_part[blockIdx.x] = sd[0];
}

__global__ void finalize_k(float* __restrict__ out) {
    __shared__ double sd[256];
    __shared__ int    si[256];
    int tid = threadIdx.x;
    double s = 0.0;
    for (int j = 0; j < 4; ++j) s += g_part[tid + 256 * j];
    sd[tid] = s;
    si[tid] = __popc(g_used[tid]);
    __syncthreads();
    for (int o = 128; o; o >>= 1) {
        if (tid < o) { sd[tid] += sd[tid + o]; si[tid] += si[tid + o]; }
        __syncthreads();
    }
    if (tid == 0) {
        float mse = (float)(sd[0] / (double)((size_t)T_TOK * DIM));
        // loss = codebook_loss + 0.25 * commitment_loss; both equal mse here
        out[(size_t)T_TOK * DIM]     = __fadd_rn(mse, __fmul_rn(0.25f, mse));
        out[(size_t)T_TOK * DIM + 1] = (float)si[0] / 8192.0f;
    }
}

// ---------------------------------------------------------------------------
extern "C" void kernel_launch(void* const* d_in, const int* in_sizes, int n_in,
                              void* d_out, int out_size) {
    const float* z  = (const float*)d_in[0];
    const float* cb = (const float*)d_in[1];
    float* out = (float*)d_out;

    cudaFuncSetAttribute((const void*)vq_argmin_k,
                         cudaFuncAttributeMaxDynamicSharedMemorySize, 81920);

    zero_used_k<<<1, 256>>>();
    row_norms_k<<<(T_TOK + K_CB) / 8, 256>>>(z, cb);
    vq_argmin_k<<<T_TOK / BM, 256, 81920>>>(z, cb);
    gather_out_k<<<T_TOK / 32, 256>>>(z, cb, out);
    finalize_k<<<1, 256>>>(out);
}

// round 3
// speedup vs baseline: 1.0006x; 1.0006x over previous
#include <cuda_runtime.h>
#include <math_constants.h>
#include <stdint.h>

#define T_TOK 32768
#define DIM   256
#define K_CB  8192
#define BM    64
#define BN    128
#define BD    16

// ---- device scratch (static: no allocations allowed) ----
__device__ float        g_x2[T_TOK];
__device__ float        g_w2[K_CB];
__device__ int          g_best[T_TOK];
__device__ unsigned int g_used[K_CB / 32];   // 256 words
__device__ double       g_part[1024];

// ---------------------------------------------------------------------------
__global__ void zero_used_k() {
    g_used[threadIdx.x] = 0u;
}

// one warp per row; rows [0,T_TOK) = z tokens (x2), [T_TOK, T_TOK+K_CB) = codebook (w2)
__global__ void row_norms_k(const float* __restrict__ z, const float* __restrict__ cb) {
    int lane = threadIdx.x & 31;
    int row  = blockIdx.x * 8 + (threadIdx.x >> 5);
    const float* p = (row < T_TOK) ? (z + (size_t)row * DIM)
                                   : (cb + (size_t)(row - T_TOK) * DIM);
    float s = 0.f;
#pragma unroll
    for (int j = 0; j < 8; ++j) {
        float v = p[lane + 32 * j];
        s = __fmaf_rn(v, v, s);
    }
#pragma unroll
    for (int off = 16; off; off >>= 1)
        s += __shfl_xor_sync(0xffffffffu, s, off);
    if (lane == 0) {
        if (row < T_TOK) g_x2[row] = s;
        else             g_w2[row - T_TOK] = s;
    }
}

// ---------------------------------------------------------------------------
// Fused distance + argmin. Block = 64 tokens; z tile resident in SMEM,
// codebook streamed in 128x16 tiles with register-prefetch double buffering.
// Each thread: 8 tokens x 4 codewords accumulator tile.
__global__ __launch_bounds__(256, 2)
void vq_argmin_k(const float* __restrict__ z, const float* __restrict__ cb) {
    extern __shared__ float smem[];
    float* as = smem;                 // [DIM][BM]  (d-major, token minor) 64KB
    float* bs = smem + DIM * BM;      // [2][BD][BN]                       16KB

    int tid  = threadIdx.x;
    int lane = tid & 31;
    int wid  = tid >> 5;              // warp 0..7 -> tokens wid*8..+8
    int t0   = blockIdx.x * BM;

    // load z tile transposed
    {
        int tt = tid & 63;
        int dc = (tid >> 6) << 6;     // 0,64,128,192
        const float4* zr = (const float4*)(z + (size_t)(t0 + tt) * DIM + dc);
#pragma unroll
        for (int i = 0; i < 16; ++i) {
            float4 v = zr[i];
            int d = dc + i * 4;
            as[(d + 0) * BM + tt] = v.x;
            as[(d + 1) * BM + tt] = v.y;
            as[(d + 2) * BM + tt] = v.z;
            as[(d + 3) * BM + tt] = v.w;
        }
    }

    float x2r[8];
#pragma unroll
    for (int i = 0; i < 8; ++i) x2r[i] = g_x2[t0 + wid * 8 + i];

    float minv[8];
    int   mini[8];
#pragma unroll
    for (int i = 0; i < 8; ++i) { minv[i] = CUDART_INF_F; mini[i] = 0; }

    int kk = tid & 127;               // codeword row loaded by this thread
    int dh = (tid >> 7) * 8;          // d-offset half: 0 or 8

    __syncthreads();

    for (int k0 = 0; k0 < K_CB; k0 += BN) {
        float acc[8][4];
#pragma unroll
        for (int i = 0; i < 8; ++i)
#pragma unroll
            for (int j = 0; j < 4; ++j) acc[i][j] = 0.f;

        const float* cbr = cb + (size_t)(k0 + kk) * DIM + dh;
        float4 r0 = *(const float4*)(cbr + 0);
        float4 r1 = *(const float4*)(cbr + 4);
        int buf = 0;

        for (int ds = 0; ds < DIM; ds += BD) {
            float* bw = bs + buf * (BD * BN);
            bw[(dh + 0) * BN + kk] = r0.x;
            bw[(dh + 1) * BN + kk] = r0.y;
            bw[(dh + 2) * BN + kk] = r0.z;
            bw[(dh + 3) * BN + kk] = r0.w;
            bw[(dh + 4) * BN + kk] = r1.x;
            bw[(dh + 5) * BN + kk] = r1.y;
            bw[(dh + 6) * BN + kk] = r1.z;
            bw[(dh + 7) * BN + kk] = r1.w;
            __syncthreads();

            if (ds + BD < DIM) {
                const float* nx = cbr + ds + BD;
                r0 = *(const float4*)(nx + 0);
                r1 = *(const float4*)(nx + 4);
            }

            const float* br = bs + buf * (BD * BN);
#pragma unroll
            for (int dd = 0; dd < BD; ++dd) {
                const float4* ap = (const float4*)(as + (ds + dd) * BM + wid * 8);
                float4 a0 = ap[0];
                float4 a1 = ap[1];
                float4 bv = *(const float4*)(br + dd * BN + lane * 4);
                float a[8] = {a0.x, a0.y, a0.z, a0.w, a1.x, a1.y, a1.z, a1.w};
                float b[4] = {bv.x, bv.y, bv.z, bv.w};
#pragma unroll
                for (int i = 0; i < 8; ++i)
#pragma unroll
                    for (int j = 0; j < 4; ++j)
                        acc[i][j] = __fmaf_rn(a[i], b[j], acc[i][j]);
            }
            buf ^= 1;
            __syncthreads();
        }

        // epilogue: mimic reference rounding: ((x2 - (2*xw)) + w2), fp32 each step
#pragma unroll
        for (int j = 0; j < 4; ++j) {
            int k = k0 + lane * 4 + j;
            float w2 = g_w2[k];
#pragma unroll
            for (int i = 0; i < 8; ++i) {
                float m    = __fmul_rn(2.0f, acc[i][j]);
                float t1   = __fsub_rn(x2r[i], m);
                float dist = __fadd_rn(t1, w2);
                if (dist < minv[i]) { minv[i] = dist; mini[i] = k; }
            }
        }
    }

    // cross-lane argmin (first-index tie-break, matching jnp.argmin)
#pragma unroll
    for (int i = 0; i < 8; ++i) {
        float v = minv[i];
        int idx = mini[i];
#pragma unroll
        for (int off = 16; off; off >>= 1) {
            float ov = __shfl_xor_sync(0xffffffffu, v, off);
            int   oi = __shfl_xor_sync(0xffffffffu, idx, off);
            if (ov < v || (ov == v && oi < idx)) { v = ov; idx = oi; }
        }
        if (lane == 0) g_best[t0 + wid * 8 + i] = idx;
    }
}

// ---------------------------------------------------------------------------
// Gather z_q, emit z_q_ste with the reference's STE round-trip rounding,
// accumulate sum((z - z_q_ste)^2) deterministically, mark used codewords.
__global__ void gather_out_k(const float* __restrict__ z, const float* __restrict__ cb,
                             float* __restrict__ out) {
    __shared__ double sd[256];
    int tid  = threadIdx.x;
    int lane = tid & 31;
    int wid  = tid >> 5;
    int tbase = blockIdx.x * 32 + wid * 4;
    double s = 0.0;

    for (int r = 0; r < 4; ++r) {
        int t   = tbase + r;
        int idx = g_best[t];
        if (lane == 0) atomicOr(&g_used[idx >> 5], 1u << (idx & 31));
        const float4* qr  = (const float4*)(cb + (size_t)idx * DIM);
        const float4* zr  = (const float4*)(z + (size_t)t * DIM);
        float4*       orow = (float4*)(out + (size_t)t * DIM);
#pragma unroll
        for (int h = 0; h < 2; ++h) {
            float4 q  = qr[lane + 32 * h];
            float4 zv = zr[lane + 32 * h];
            float4 o;
            o.x = __fadd_rn(zv.x, __fsub_rn(q.x, zv.x));
            o.y = __fadd_rn(zv.y, __fsub_rn(q.y, zv.y));
            o.z = __fadd_rn(zv.z, __fsub_rn(q.z, zv.z));
            o.w = __fadd_rn(zv.w, __fsub_rn(q.w, zv.w));
            orow[lane + 32 * h] = o;
            float dx = __fsub_rn(zv.x, o.x);
            float dy = __fsub_rn(zv.y, o.y);
            float dz = __fsub_rn(zv.z, o.z);
            float dw = __fsub_rn(zv.w, o.w);
            s += (double)__fmul_rn(dx, dx);
            s += (double)__fmul_rn(dy, dy);
            s += (double)__fmul_rn(dz, dz);
            s += (double)__fmul_rn(dw, dw);
        }
    }
    sd[tid] = s;
    __syncthreads();
    for (int o = 128; o; o >>= 1) {
        if (tid < o) sd[tid] += sd[tid + o];
        __syncthreads();
    }
    if (tid == 0) g_part[blockIdx.x] = sd[0];
}

__global__ void finalize_k(float* __restrict__ out) {
    __shared__ double sd[256];
    __shared__ int    si[256];
    int tid = threadIdx.x;
    double s = 0.0;
    for (int j = 0; j < 4; ++j) s += g_part[tid + 256 * j];
    sd[tid] = s;
    si[tid] = __popc(g_used[tid]);
    __syncthreads();
    for (int o = 128; o; o >>= 1) {
        if (tid < o) { sd[tid] += sd[tid + o]; si[tid] += si[tid + o]; }
        __syncthreads();
    }
    if (tid == 0) {
        float mse = (float)(sd[0] / (double)((size_t)T_TOK * DIM));
        // loss = codebook_loss + 0.25 * commitment_loss; both equal mse here
        out[(size_t)T_TOK * DIM]     = __fadd_rn(mse, __fmul_rn(0.25f, mse));
        out[(size_t)T_TOK * DIM + 1] = (float)si[0] / 8192.0f;
    }
}

// ---------------------------------------------------------------------------
extern "C" void kernel_launch(void* const* d_in, const int* in_sizes, int n_in,
                              void* d_out, int out_size) {
    const float* z  = (const float*)d_in[0];
    const float* cb = (const float*)d_in[1];
    float* out = (float*)d_out;

    cudaFuncSetAttribute((const void*)vq_argmin_k,
                         cudaFuncAttributeMaxDynamicSharedMemorySize, 81920);

    zero_used_k<<<1, 256>>>();
    row_norms_k<<<(T_TOK + K_CB) / 8, 256>>>(z, cb);
    vq_argmin_k<<<T_TOK / BM, 256, 81920>>>(z, cb);
    gather_out_k<<<T_TOK / 32, 256>>>(z, cb, out);
    finalize_k<<<1, 256>>>(out);
}

// round 15
// speedup vs baseline: 3.2929x; 3.2908x over previous
#include <cuda_runtime.h>
#include <cuda_bf16.h>
#include <math_constants.h>
#include <stdint.h>

#define T_TOK 32768
#define DIM   256
#define K_CB  8192
#define CAP   (8*1024*1024)
#define MARGIN 5.0e-4f

typedef unsigned int u32;
typedef unsigned long long u64;

// ---- static device scratch ----
__device__ float g_x2[T_TOK];
__device__ float g_w2[K_CB];
__device__ __align__(16) u32 g_wbf2[K_CB * DIM / 2];   // codebook bf16x2, 4MB
__device__ u32  g_pairs[CAP];
__device__ u32  g_napp;
__device__ u64  g_best64[T_TOK];
__device__ u32  g_used[K_CB / 32];
__device__ double g_part[1024];

// ---------------------------------------------------------------------------
__global__ void init_k() {
    int i = blockIdx.x * 256 + threadIdx.x;          // grid 128
    g_best64[i] = ~0ull;
    if (blockIdx.x == 0) {
        g_used[threadIdx.x] = 0u;
        if (threadIdx.x == 0) g_napp = 0u;
    }
}

// codebook fp32 -> bf16x2  (grid 2048 -> 524288 float4 = K_CB*DIM/4)
__global__ void cvt_cb_k(const float* __restrict__ cb) {
    int i = blockIdx.x * 256 + threadIdx.x;
    float4 f = ((const float4*)cb)[i];
    __nv_bfloat16 b0 = __float2bfloat16_rn(f.x);
    __nv_bfloat16 b1 = __float2bfloat16_rn(f.y);
    __nv_bfloat16 b2 = __float2bfloat16_rn(f.z);
    __nv_bfloat16 b3 = __float2bfloat16_rn(f.w);
    u32 lo = (u32)*reinterpret_cast<unsigned short*>(&b0) |
             ((u32)*reinterpret_cast<unsigned short*>(&b1) << 16);
    u32 hi = (u32)*reinterpret_cast<unsigned short*>(&b2) |
             ((u32)*reinterpret_cast<unsigned short*>(&b3) << 16);
    g_wbf2[i * 2]     = lo;
    g_wbf2[i * 2 + 1] = hi;
}

// one warp per row; rows [0,T) = z (x2), [T, T+K) = codebook (w2)
__global__ void row_norms_k(const float* __restrict__ z, const float* __restrict__ cb) {
    int lane = threadIdx.x & 31;
    int row  = blockIdx.x * 8 + (threadIdx.x >> 5);
    const float* p = (row < T_TOK) ? (z + (size_t)row * DIM)
                                   : (cb + (size_t)(row - T_TOK) * DIM);
    float s = 0.f;
#pragma unroll
    for (int j = 0; j < 8; ++j) {
        float v = p[lane + 32 * j];
        s = __fmaf_rn(v, v, s);
    }
#pragma unroll
    for (int off = 16; off; off >>= 1)
        s += __shfl_xor_sync(0xffffffffu, s, off);
    if (lane == 0) {
        if (row < T_TOK) g_x2[row] = s;
        else             g_w2[row - T_TOK] = s;
    }
}

// ---------------------------------------------------------------------------
#define CP_ASYNC16(dst, src) \
    asm volatile("cp.async.cg.shared.global [%0], [%1], 16;\n" :: "r"(dst), "l"(src))
#define CP_COMMIT() asm volatile("cp.async.commit_group;\n" ::: "memory")
#define CP_WAIT1()  asm volatile("cp.async.wait_group 1;\n" ::: "memory")
#define CP_WAIT0()  asm volatile("cp.async.wait_group 0;\n" ::: "memory")

#define MMA16816(C, A, b0_, b1_) \
    asm volatile("mma.sync.aligned.m16n8k16.row.col.f32.bf16.bf16.f32 " \
        "{%0,%1,%2,%3}, {%4,%5,%6,%7}, {%8,%9}, {%0,%1,%2,%3};" \
        : "+f"(C[0]), "+f"(C[1]), "+f"(C[2]), "+f"(C[3]) \
        : "r"(A.x), "r"(A.y), "r"(A.z), "r"(A.w), "r"(b0_), "r"(b1_))

// bf16 tensor-core screen.
// Block: 256 tokens x all K. 8 warps, each warp = 32 tokens x 128-cw chunk.
// SMEM: A fragments [16 m_tile][16 kstep][32 lane][4] u32 = 128KB (packed once),
//       B fragments double-buffered [2][16 n_tile][8 ks][2 j][32 lane] u32 = 64KB,
//       filled by cp.async with a granule permutation (16B src -> 16B dst).
__global__ __launch_bounds__(256, 1)
void screen_k(const float* __restrict__ z) {
    extern __shared__ u32 smem[];
    u32* Af = smem;                   // 32768 u32
    u32* Bf = smem + 32768;           // 2 * 8192 u32

    const int tid  = threadIdx.x;
    const int lane = tid & 31;
    const int wrp  = tid >> 5;        // 0..7 : tokens wrp*32..+32
    const int g    = lane >> 2;       // 0..7
    const int tq   = lane & 3;        // 0..3
    const int t0   = blockIdx.x * 256;

    // ---- pack A (z rows -> mma fragment layout, bf16) ----
#pragma unroll 4
    for (int i = 0; i < 128; ++i) {
        int p   = tid + 256 * i;
        int row = p >> 7;             // 0..255
        int w_  = p & 127;            // d/2
        float2 f = *(const float2*)(z + (size_t)(t0 + row) * DIM + w_ * 2);
        __nv_bfloat16 a0 = __float2bfloat16_rn(f.x);
        __nv_bfloat16 a1 = __float2bfloat16_rn(f.y);
        u32 v = (u32)*reinterpret_cast<unsigned short*>(&a0) |
                ((u32)*reinterpret_cast<unsigned short*>(&a1) << 16);
        int mt = row >> 4, rr = row & 15, hb = rr >> 3, gg = rr & 7;
        int ks = w_ >> 3, w8 = w_ & 7, jl = w8 >> 2, tt = w8 & 3;
        Af[(((mt * 16 + ks) * 32 + gg * 4 + tt) << 2) + (hb + 2 * jl)] = v;
    }

    u32 bsmem = (u32)__cvta_generic_to_shared(Bf);

    float acc[2][16][4];
#pragma unroll
    for (int mi = 0; mi < 2; ++mi)
#pragma unroll
        for (int ni = 0; ni < 16; ++ni)
#pragma unroll
            for (int c = 0; c < 4; ++c) acc[mi][ni][c] = 0.f;

    float rmax[4] = {-CUDART_INF_F, -CUDART_INF_F, -CUDART_INF_F, -CUDART_INF_F};
    const int tokb = t0 + wrp * 32 + g;

    // issue stage 0 copy
    {
        int k0 = 0, h = 0;
#pragma unroll
        for (int i = 0; i < 8; ++i) {
            int G  = tid + (i << 8);
            int gg = G & 7, j = (G >> 3) & 1, ks = (G >> 4) & 7, nt = G >> 7;
            int cw = k0 + nt * 8 + gg;
            const u32* src = g_wbf2 + (size_t)cw * 128 + (h * 8 + ks) * 8 + j * 4;
            u32 dst = bsmem + (((((nt * 8 + ks) * 2 + j) * 32 + gg * 4)) << 2);
            CP_ASYNC16(dst, src);
        }
        CP_COMMIT();
    }

    for (int s = 0; s < 128; ++s) {
        int k0 = (s >> 1) << 7;
        int h  = s & 1;

        if (s + 1 < 128) {
            int k0n = ((s + 1) >> 1) << 7;
            int hn  = (s + 1) & 1;
            u32 dbase = bsmem + (((s + 1) & 1) << 15);
#pragma unroll
            for (int i = 0; i < 8; ++i) {
                int G  = tid + (i << 8);
                int gg = G & 7, j = (G >> 3) & 1, ks = (G >> 4) & 7, nt = G >> 7;
                int cw = k0n + nt * 8 + gg;
                const u32* src = g_wbf2 + (size_t)cw * 128 + (hn * 8 + ks) * 8 + j * 4;
                u32 dst = dbase + ((((nt * 8 + ks) * 2 + j) * 32 + gg * 4) << 2);
                CP_ASYNC16(dst, src);
            }
            CP_COMMIT();
            CP_WAIT1();
        } else {
            CP_WAIT0();
        }
        __syncthreads();

        const u32* Bc = Bf + ((s & 1) << 13);
#pragma unroll
        for (int ks = 0; ks < 8; ++ks) {
            int kg = h * 8 + ks;
            uint4 A0 = *(const uint4*)(Af + ((wrp * 2 + 0) * 16 + kg) * 128 + lane * 4);
            uint4 A1 = *(const uint4*)(Af + ((wrp * 2 + 1) * 16 + kg) * 128 + lane * 4);
#pragma unroll
            for (int ni = 0; ni < 16; ++ni) {
                u32 b0 = Bc[((ni * 8 + ks) * 2 + 0) * 32 + lane];
                u32 b1 = Bc[((ni * 8 + ks) * 2 + 1) * 32 + lane];
                MMA16816(acc[0][ni], A0, b0, b1);
                MMA16816(acc[1][ni], A1, b0, b1);
            }
        }

        if (h == 1) {
            // ---- chunk epilogue: running max + margin appends ----
            float cmax[4] = {-CUDART_INF_F, -CUDART_INF_F, -CUDART_INF_F, -CUDART_INF_F};
#pragma unroll
            for (int mi = 0; mi < 2; ++mi)
#pragma unroll
                for (int ni = 0; ni < 16; ++ni) {
                    float mlo = fmaxf(acc[mi][ni][0], acc[mi][ni][1]);
                    float mhi = fmaxf(acc[mi][ni][2], acc[mi][ni][3]);
                    cmax[mi * 2]     = fmaxf(cmax[mi * 2], mlo);
                    cmax[mi * 2 + 1] = fmaxf(cmax[mi * 2 + 1], mhi);
                }
            float thr[4];
#pragma unroll
            for (int r = 0; r < 4; ++r) {
                float v = cmax[r];
                v = fmaxf(v, __shfl_xor_sync(0xffffffffu, v, 1));
                v = fmaxf(v, __shfl_xor_sync(0xffffffffu, v, 2));
                rmax[r] = fmaxf(rmax[r], v);
                thr[r]  = rmax[r] - MARGIN;
            }
#pragma unroll
            for (int mi = 0; mi < 2; ++mi) {
                float tmin = fminf(thr[mi * 2], thr[mi * 2 + 1]);
#pragma unroll
                for (int ni = 0; ni < 16; ++ni) {
                    float g4 = fmaxf(fmaxf(acc[mi][ni][0], acc[mi][ni][1]),
                                     fmaxf(acc[mi][ni][2], acc[mi][ni][3]));
                    if (g4 >= tmin) {
#pragma unroll
                        for (int c = 0; c < 4; ++c) {
                            if (acc[mi][ni][c] >= thr[mi * 2 + (c >> 1)]) {
                                int token = tokb + mi * 16 + ((c >> 1) << 3);
                                int cw    = k0 + ni * 8 + 2 * tq + (c & 1);
                                u32 idx = atomicAdd(&g_napp, 1u);
                                if (idx < CAP)
                                    g_pairs[idx] = ((u32)token << 13) | (u32)cw;
                            }
                        }
                    }
                    acc[mi][ni][0] = 0.f; acc[mi][ni][1] = 0.f;
                    acc[mi][ni][2] = 0.f; acc[mi][ni][3] = 0.f;
                }
            }
        }
        __syncthreads();
    }
}

// ---------------------------------------------------------------------------
// Exact fp32 rescore of candidate pairs; epilogue rounding identical to R1:
// dist = fl(fl(x2 - fl(2*xw)) + w2). Winner via atomicMin on (dist_bits<<32|k)
// -> exact lowest-index tie-break, order-invariant (deterministic).
__global__ void rescore_k(const float* __restrict__ z, const float* __restrict__ cb) {
    u32 n = *((volatile u32*)&g_napp);
    if (n > CAP) n = CAP;
    int lane = threadIdx.x & 31;
    int wg   = (blockIdx.x * blockDim.x + threadIdx.x) >> 5;
    int nwg  = (gridDim.x * blockDim.x) >> 5;
    for (u32 p = wg; p < n; p += nwg) {
        u32 pr = g_pairs[p];
        int t = pr >> 13, k = pr & 8191;
        const float4* zr = (const float4*)(z + (size_t)t * DIM);
        const float4* cr = (const float4*)(cb + (size_t)k * DIM);
        float s = 0.f;
#pragma unroll
        for (int hh = 0; hh < 2; ++hh) {
            float4 a = zr[lane + 32 * hh];
            float4 b = cr[lane + 32 * hh];
            s = __fmaf_rn(a.x, b.x, s);
            s = __fmaf_rn(a.y, b.y, s);
            s = __fmaf_rn(a.z, b.z, s);
            s = __fmaf_rn(a.w, b.w, s);
        }
#pragma unroll
        for (int o = 16; o; o >>= 1)
            s += __shfl_xor_sync(0xffffffffu, s, o);
        if (lane == 0) {
            float m    = __fmul_rn(2.0f, s);
            float t1   = __fsub_rn(g_x2[t], m);
            float dist = __fadd_rn(t1, g_w2[k]);
            u64 pk = ((u64)__float_as_uint(dist) << 32) | (u32)k;
            atomicMin(&g_best64[t], pk);
        }
    }
}

// ---------------------------------------------------------------------------
__global__ void gather_out_k(const float* __restrict__ z, const float* __restrict__ cb,
                             float* __restrict__ out) {
    __shared__ double sd[256];
    int tid  = threadIdx.x;
    int lane = tid & 31;
    int wid  = tid >> 5;
    int tbase = blockIdx.x * 32 + wid * 4;
    double s = 0.0;

    for (int r = 0; r < 4; ++r) {
        int t   = tbase + r;
        int idx = (int)(g_best64[t] & 0xffffffffull);
        idx &= 8191;   // defensive: no-op when best64 is valid
        if (lane == 0) atomicOr(&g_used[idx >> 5], 1u << (idx & 31));
        const float4* qr  = (const float4*)(cb + (size_t)idx * DIM);
        const float4* zr  = (const float4*)(z + (size_t)t * DIM);
        float4*       orow = (float4*)(out + (size_t)t * DIM);
#pragma unroll
        for (int h = 0; h < 2; ++h) {
            float4 q  = qr[lane + 32 * h];
            float4 zv = zr[lane + 32 * h];
            float4 o;
            o.x = __fadd_rn(zv.x, __fsub_rn(q.x, zv.x));
            o.y = __fadd_rn(zv.y, __fsub_rn(q.y, zv.y));
            o.z = __fadd_rn(zv.z, __fsub_rn(q.z, zv.z));
            o.w = __fadd_rn(zv.w, __fsub_rn(q.w, zv.w));
            orow[lane + 32 * h] = o;
            float dx = __fsub_rn(zv.x, o.x);
            float dy = __fsub_rn(zv.y, o.y);
            float dz = __fsub_rn(zv.z, o.z);
            float dw = __fsub_rn(zv.w, o.w);
            s += (double)__fmul_rn(dx, dx);
            s += (double)__fmul_rn(dy, dy);
            s += (double)__fmul_rn(dz, dz);
            s += (double)__fmul_rn(dw, dw);
        }
    }
    sd[tid] = s;
    __syncthreads();
    for (int o = 128; o; o >>= 1) {
        if (tid < o) sd[tid] += sd[tid + o];
        __syncthreads();
    }
    if (tid == 0) g_part[blockIdx.x] = sd[0];
}

__global__ void finalize_k(float* __restrict__ out) {
    __shared__ double sd[256];
    __shared__ int    si[256];
    int tid = threadIdx.x;
    double s = 0.0;
    for (int j = 0; j < 4; ++j) s += g_part[tid + 256 * j];
    sd[tid] = s;
    si[tid] = __popc(g_used[tid]);
    __syncthreads();
    for (int o = 128; o; o >>= 1) {
        if (tid < o) { sd[tid] += sd[tid + o]; si[tid] += si[tid + o]; }
        __syncthreads();
    }
    if (tid == 0) {
        float mse = (float)(sd[0] / (double)((size_t)T_TOK * DIM));
        out[(size_t)T_TOK * DIM]     = __fadd_rn(mse, __fmul_rn(0.25f, mse));
        out[(size_t)T_TOK * DIM + 1] = (float)si[0] / 8192.0f;
    }
}

// ---------------------------------------------------------------------------
extern "C" void kernel_launch(void* const* d_in, const int* in_sizes, int n_in,
                              void* d_out, int out_size) {
    const float* z  = (const float*)d_in[0];
    const float* cb = (const float*)d_in[1];
    float* out = (float*)d_out;

    cudaFuncSetAttribute((const void*)screen_k,
                         cudaFuncAttributeMaxDynamicSharedMemorySize, 196608);

    init_k<<<128, 256>>>();
    cvt_cb_k<<<2048, 256>>>(cb);
    row_norms_k<<<(T_TOK + K_CB) / 8, 256>>>(z, cb);
    screen_k<<<128, 256, 196608>>>(z);
    rescore_k<<<1024, 256>>>(z, cb);
    gather_out_k<<<T_TOK / 32, 256>>>(z, cb, out);
    finalize_k<<<1, 256>>>(out);
}